// round 1
// baseline (speedup 1.0000x reference)
#include <cuda_runtime.h>
#include <cstdint>

#define N_NODES 50000
#define N_EDGES 800000
#define D_HID   128

// ---------------- scratch (static __device__ globals; no allocation) ----------------
__device__ int   g_deg [N_NODES];
__device__ int   g_off [N_NODES + 1];
__device__ int   g_pos [N_NODES];
__device__ int   g_srcs[N_EDGES];
__device__ float g_inv [N_NODES];
__device__ float g_mean[(size_t)N_NODES * D_HID];
__device__ float g_h1  [(size_t)N_NODES * D_HID];
__device__ float g_h2  [(size_t)N_NODES * D_HID];

using ull = unsigned long long;

__device__ __forceinline__ ull pack2(float lo, float hi) {
    ull r;
    asm("mov.b64 %0, {%1, %2};" : "=l"(r) : "f"(lo), "f"(hi));
    return r;
}
__device__ __forceinline__ void fma2(ull& d, ull a, ull b) {
    asm("fma.rn.f32x2 %0, %1, %2, %0;" : "+l"(d) : "l"(a), "l"(b));
}
__device__ __forceinline__ float2 unpack2(ull v) {
    float2 r;
    asm("mov.b64 {%0, %1}, %2;" : "=f"(r.x), "=f"(r.y) : "l"(v));
    return r;
}

// ---------------- CSR build ----------------
__global__ void k_zero_deg() {
    int i = blockIdx.x * blockDim.x + threadIdx.x;
    if (i < N_NODES) g_deg[i] = 0;
}

__global__ void k_count(const int* __restrict__ dst) {
    int e = blockIdx.x * blockDim.x + threadIdx.x;
    if (e < N_EDGES) atomicAdd(&g_deg[dst[e]], 1);
}

// single-block exclusive scan over degrees; also emits inv_deg and scatter cursors
__global__ void k_scan() {
    __shared__ int sbuf[1024];
    __shared__ int carry;
    int t = threadIdx.x;
    if (t == 0) carry = 0;
    __syncthreads();
    for (int base = 0; base < N_NODES; base += 1024) {
        int i = base + t;
        int v = (i < N_NODES) ? g_deg[i] : 0;
        sbuf[t] = v;
        __syncthreads();
        #pragma unroll
        for (int off = 1; off < 1024; off <<= 1) {
            int x = (t >= off) ? sbuf[t - off] : 0;
            __syncthreads();
            sbuf[t] += x;
            __syncthreads();
        }
        int incl = sbuf[t] + carry;
        if (i < N_NODES) {
            g_off[i + 1] = incl;
            g_pos[i]     = incl - v;           // exclusive start == scatter cursor
            g_inv[i]     = (v > 0) ? (1.0f / (float)v) : 0.0f;
        }
        if (i == 0) g_off[0] = 0;
        __syncthreads();
        if (t == 1023) carry = incl;
        __syncthreads();
    }
}

__global__ void k_scatter(const int* __restrict__ src, const int* __restrict__ dst) {
    int e = blockIdx.x * blockDim.x + threadIdx.x;
    if (e < N_EDGES) {
        int d = dst[e];
        int p = atomicAdd(&g_pos[d], 1);
        g_srcs[p] = src[e];
    }
}

// ---------------- mean aggregation: one warp per node ----------------
__global__ void k_agg(const float* __restrict__ h) {
    int w    = (blockIdx.x * blockDim.x + threadIdx.x) >> 5;
    int lane = threadIdx.x & 31;
    if (w >= N_NODES) return;

    int e  = g_off[w];
    int e1 = g_off[w + 1];
    float4 acc = make_float4(0.f, 0.f, 0.f, 0.f);
    const float* base = h + lane * 4;

    for (; e + 1 < e1; e += 2) {
        int s0 = g_srcs[e];
        int s1 = g_srcs[e + 1];
        float4 v0 = *(const float4*)(base + (size_t)s0 * D_HID);
        float4 v1 = *(const float4*)(base + (size_t)s1 * D_HID);
        acc.x += v0.x + v1.x;
        acc.y += v0.y + v1.y;
        acc.z += v0.z + v1.z;
        acc.w += v0.w + v1.w;
    }
    if (e < e1) {
        int s = g_srcs[e];
        float4 v = *(const float4*)(base + (size_t)s * D_HID);
        acc.x += v.x; acc.y += v.y; acc.z += v.z; acc.w += v.w;
    }

    float inv = g_inv[w];
    float4 o = make_float4(acc.x * inv, acc.y * inv, acc.z * inv, acc.w * inv);
    *(float4*)(g_mean + (size_t)w * D_HID + lane * 4) = o;
}

// ---------------- fused dual-GEMM + bias + relu ----------------
// out[r, j] = relu( sum_k A[r,k]*Wl[j,k] + bias[j] + sum_k H[r,k]*Wr[j,k] )
// A, H: [N, 128] row-major. Wl, Wr: [J, 128] row-major. out: [N, J].
// BM=128 rows/block, 256 threads, thread tile 8 x TN, packed f32x2 FMAs.
template <int J, int TN>
__global__ __launch_bounds__(256, 2) void k_gemm(
    const float* __restrict__ A, const float* __restrict__ H,
    const float* __restrict__ Wl, const float* __restrict__ bias,
    const float* __restrict__ Wr, float* __restrict__ out)
{
    constexpr int BM = 128, BK = 32, TM = 8;
    constexpr int NP = TN / 2;
    constexpr int WPAD = (TN == 8) ? 132 : 33;

    __shared__ float As[BK][132];   // [k][m], stride 132 keeps LDS.128 alignment + no bank conflicts
    __shared__ float Ws[BK][WPAD];  // [k][j]

    const int t    = threadIdx.x;
    const int ct   = t & 15;        // 16 column-thread groups
    const int rt   = t >> 4;        // 16 row-thread groups
    const int tn0  = ct * TN;
    const int tm0  = rt * TM;
    const int row0 = blockIdx.x * BM;

    ull acc[TM][NP];
    #pragma unroll
    for (int m = 0; m < TM; m++)
        #pragma unroll
        for (int p = 0; p < NP; p++) acc[m][p] = 0ull;

    #pragma unroll
    for (int phase = 0; phase < 2; phase++) {
        const float* Ap = phase ? H  : A;
        const float* Wp = phase ? Wr : Wl;

        for (int kc = 0; kc < 128; kc += BK) {
            __syncthreads();
            // A tile: 128 rows x 32 k-cols, transposed into As[k][m]
            #pragma unroll
            for (int i = 0; i < 4; i++) {
                int li = t + i * 256;
                int m  = li >> 3;
                int kq = li & 7;
                int r  = row0 + m;
                float4 v = make_float4(0.f, 0.f, 0.f, 0.f);
                if (r < N_NODES)
                    v = *(const float4*)(Ap + (size_t)r * 128 + kc + kq * 4);
                As[kq * 4 + 0][m] = v.x;
                As[kq * 4 + 1][m] = v.y;
                As[kq * 4 + 2][m] = v.z;
                As[kq * 4 + 3][m] = v.w;
            }
            // W tile: J rows x 32 k-cols, transposed into Ws[k][j]
            #pragma unroll
            for (int i = 0; i < J / 32; i++) {
                int li = t + i * 256;
                int j  = li >> 3;
                int kq = li & 7;
                float4 v = *(const float4*)(Wp + j * 128 + kc + kq * 4);
                Ws[kq * 4 + 0][j] = v.x;
                Ws[kq * 4 + 1][j] = v.y;
                Ws[kq * 4 + 2][j] = v.z;
                Ws[kq * 4 + 3][j] = v.w;
            }
            __syncthreads();

            #pragma unroll
            for (int k = 0; k < BK; k++) {
                float4 a0 = *(const float4*)&As[k][tm0];
                float4 a1 = *(const float4*)&As[k][tm0 + 4];
                ull ap[TM];
                ap[0] = pack2(a0.x, a0.x);
                ap[1] = pack2(a0.y, a0.y);
                ap[2] = pack2(a0.z, a0.z);
                ap[3] = pack2(a0.w, a0.w);
                ap[4] = pack2(a1.x, a1.x);
                ap[5] = pack2(a1.y, a1.y);
                ap[6] = pack2(a1.z, a1.z);
                ap[7] = pack2(a1.w, a1.w);

                ull wv[NP];
                if constexpr (TN == 8) {
                    ulonglong2 w01 = *(const ulonglong2*)&Ws[k][tn0];
                    ulonglong2 w23 = *(const ulonglong2*)&Ws[k][tn0 + 4];
                    wv[0] = w01.x; wv[1] = w01.y; wv[2] = w23.x; wv[3] = w23.y;
                } else {
                    wv[0] = pack2(Ws[k][tn0], Ws[k][tn0 + 1]);
                }

                #pragma unroll
                for (int m = 0; m < TM; m++)
                    #pragma unroll
                    for (int p = 0; p < NP; p++)
                        fma2(acc[m][p], ap[m], wv[p]);
            }
        }
    }

    // epilogue: bias + relu + store
    float bv[TN];
    #pragma unroll
    for (int q = 0; q < TN; q++) bv[q] = bias[tn0 + q];

    #pragma unroll
    for (int m = 0; m < TM; m++) {
        int r = row0 + tm0 + m;
        if (r < N_NODES) {
            float o[TN];
            #pragma unroll
            for (int p = 0; p < NP; p++) {
                float2 v = unpack2(acc[m][p]);
                o[2 * p + 0] = fmaxf(v.x + bv[2 * p + 0], 0.f);
                o[2 * p + 1] = fmaxf(v.y + bv[2 * p + 1], 0.f);
            }
            if constexpr (TN == 8) {
                *(float4*)(out + (size_t)r * J + tn0)     = make_float4(o[0], o[1], o[2], o[3]);
                *(float4*)(out + (size_t)r * J + tn0 + 4) = make_float4(o[4], o[5], o[6], o[7]);
            } else {
                *(float2*)(out + (size_t)r * J + tn0) = make_float2(o[0], o[1]);
            }
        }
    }
}

// ---------------- launch ----------------
extern "C" void kernel_launch(void* const* d_in, const int* in_sizes, int n_in,
                              void* d_out, int out_size) {
    const float* x   = (const float*)d_in[0];
    const int*   ei  = (const int*)d_in[1];
    const float* Wl1 = (const float*)d_in[2];
    const float* bl1 = (const float*)d_in[3];
    const float* Wr1 = (const float*)d_in[4];
    const float* Wl2 = (const float*)d_in[5];
    const float* bl2 = (const float*)d_in[6];
    const float* Wr2 = (const float*)d_in[7];
    const float* Wl3 = (const float*)d_in[8];
    const float* bl3 = (const float*)d_in[9];
    const float* Wr3 = (const float*)d_in[10];
    float* out = (float*)d_out;

    const int* src = ei;
    const int* dst = ei + N_EDGES;

    float *mean_p, *h1_p, *h2_p;
    cudaGetSymbolAddress((void**)&mean_p, g_mean);
    cudaGetSymbolAddress((void**)&h1_p,   g_h1);
    cudaGetSymbolAddress((void**)&h2_p,   g_h2);

    const int EB = (N_EDGES + 255) / 256;          // 3125
    const int AB = (N_NODES * 32 + 255) / 256;     // 6250 (warp per node)
    const int GB = (N_NODES + 127) / 128;          // 391

    // CSR build (shared by all 3 layers)
    k_zero_deg<<<(N_NODES + 255) / 256, 256>>>();
    k_count<<<EB, 256>>>(dst);
    k_scan<<<1, 1024>>>();
    k_scatter<<<EB, 256>>>(src, dst);

    // layer 1
    k_agg<<<AB, 256>>>(x);
    k_gemm<128, 8><<<GB, 256>>>(mean_p, x, Wl1, bl1, Wr1, h1_p);
    // layer 2
    k_agg<<<AB, 256>>>(h1_p);
    k_gemm<128, 8><<<GB, 256>>>(mean_p, h1_p, Wl2, bl2, Wr2, h2_p);
    // layer 3
    k_agg<<<AB, 256>>>(h2_p);
    k_gemm<32, 2><<<GB, 256>>>(mean_p, h2_p, Wl3, bl3, Wr3, out);
}

// round 3
// speedup vs baseline: 1.2419x; 1.2419x over previous
#include <cuda_runtime.h>
#include <cstdint>

#define N_NODES 50000
#define N_EDGES 800000
#define D_HID   128
#define SCAN_B  49   // ceil(50000/1024)

// ---------------- scratch (static __device__ globals; no allocation) ----------------
__device__ int   g_deg [N_NODES];
__device__ int   g_off [N_NODES + 1];
__device__ int   g_pos [N_NODES];
__device__ int   g_srcs[N_EDGES];
__device__ float g_inv [N_NODES];
__device__ int   g_bsum[64];
__device__ int   g_bpre[64];
__device__ float g_mean[(size_t)N_NODES * D_HID];
__device__ float g_h1  [(size_t)N_NODES * D_HID];
__device__ float g_h2  [(size_t)N_NODES * D_HID];
__device__ float g_p   [(size_t)N_NODES * 32];
__device__ float g_q   [(size_t)N_NODES * 32];

using ull = unsigned long long;

__device__ __forceinline__ ull pack2(float lo, float hi) {
    ull r;
    asm("mov.b64 %0, {%1, %2};" : "=l"(r) : "f"(lo), "f"(hi));
    return r;
}
__device__ __forceinline__ void fma2(ull& d, ull a, ull b) {
    asm("fma.rn.f32x2 %0, %1, %2, %0;" : "+l"(d) : "l"(a), "l"(b));
}
__device__ __forceinline__ float2 unpack2(ull v) {
    float2 r;
    asm("mov.b64 {%0, %1}, %2;" : "=f"(r.x), "=f"(r.y) : "l"(v));
    return r;
}

// ---------------- CSR build ----------------
__global__ void k_zero_deg() {
    int i = blockIdx.x * blockDim.x + threadIdx.x;
    if (i < N_NODES) g_deg[i] = 0;
}

__global__ void k_count(const int* __restrict__ dst) {
    int e = blockIdx.x * blockDim.x + threadIdx.x;
    if (e < N_EDGES) atomicAdd(&g_deg[dst[e]], 1);
}

// block-local inclusive scan of degrees (49 blocks x 1024)
__global__ void k_scan1() {
    __shared__ int wsum[32];
    int t = threadIdx.x, b = blockIdx.x;
    int i = b * 1024 + t;
    int v = (i < N_NODES) ? g_deg[i] : 0;
    int lane = t & 31, w = t >> 5;
    int x = v;
    #pragma unroll
    for (int o = 1; o < 32; o <<= 1) {
        int y = __shfl_up_sync(0xffffffffu, x, o);
        if (lane >= o) x += y;
    }
    if (lane == 31) wsum[w] = x;
    __syncthreads();
    if (w == 0) {
        int s = wsum[lane];
        #pragma unroll
        for (int o = 1; o < 32; o <<= 1) {
            int y = __shfl_up_sync(0xffffffffu, s, o);
            if (lane >= o) s += y;
        }
        wsum[lane] = s;
    }
    __syncthreads();
    int incl = x + (w > 0 ? wsum[w - 1] : 0);
    if (i < N_NODES) {
        g_off[i + 1] = incl;                         // block-local inclusive
        g_inv[i] = (v > 0) ? (1.0f / (float)v) : 0.0f;
    }
    if (t == 1023) g_bsum[b] = incl;
}

// scan block sums (1 block, 64 threads)
__global__ void k_scan2() {
    __shared__ int buf[2];
    int t = threadIdx.x;
    if (t < 2) buf[t] = 0;
    __syncthreads();
    int v = (t < SCAN_B) ? g_bsum[t] : 0;
    int lane = t & 31, w = t >> 5;
    int x = v;
    #pragma unroll
    for (int o = 1; o < 32; o <<= 1) {
        int y = __shfl_up_sync(0xffffffffu, x, o);
        if (lane >= o) x += y;
    }
    if (lane == 31) buf[w] = x;
    __syncthreads();
    if (w == 1) x += buf[0];
    if (t < SCAN_B) g_bpre[t] = x - v;               // exclusive block prefix
}

// add block prefixes; emit final offsets + scatter cursors
__global__ void k_scan3() {
    int i = blockIdx.x * blockDim.x + threadIdx.x;
    if (i < N_NODES) {
        int o = g_off[i + 1] + g_bpre[i >> 10];
        g_off[i + 1] = o;
        g_pos[i] = o - g_deg[i];
    }
    if (i == 0) g_off[0] = 0;
}

__global__ void k_scatter(const int* __restrict__ src, const int* __restrict__ dst) {
    int e = blockIdx.x * blockDim.x + threadIdx.x;
    if (e < N_EDGES) {
        int d = dst[e];
        int p = atomicAdd(&g_pos[d], 1);
        g_srcs[p] = src[e];
    }
}

// ---------------- mean aggregation (128-d): one warp per node ----------------
__global__ void k_agg(const float* __restrict__ h) {
    int w    = (blockIdx.x * blockDim.x + threadIdx.x) >> 5;
    int lane = threadIdx.x & 31;
    if (w >= N_NODES) return;

    int e  = g_off[w];
    int e1 = g_off[w + 1];
    float4 acc = make_float4(0.f, 0.f, 0.f, 0.f);
    const float* base = h + lane * 4;

    for (; e + 3 < e1; e += 4) {
        int s0 = g_srcs[e], s1 = g_srcs[e + 1], s2 = g_srcs[e + 2], s3 = g_srcs[e + 3];
        float4 v0 = *(const float4*)(base + (size_t)s0 * D_HID);
        float4 v1 = *(const float4*)(base + (size_t)s1 * D_HID);
        float4 v2 = *(const float4*)(base + (size_t)s2 * D_HID);
        float4 v3 = *(const float4*)(base + (size_t)s3 * D_HID);
        acc.x += (v0.x + v1.x) + (v2.x + v3.x);
        acc.y += (v0.y + v1.y) + (v2.y + v3.y);
        acc.z += (v0.z + v1.z) + (v2.z + v3.z);
        acc.w += (v0.w + v1.w) + (v2.w + v3.w);
    }
    for (; e < e1; e++) {
        int s = g_srcs[e];
        float4 v = *(const float4*)(base + (size_t)s * D_HID);
        acc.x += v.x; acc.y += v.y; acc.z += v.z; acc.w += v.w;
    }

    float inv = g_inv[w];
    *(float4*)(g_mean + (size_t)w * D_HID + lane * 4) =
        make_float4(acc.x * inv, acc.y * inv, acc.z * inv, acc.w * inv);
}

// ---------------- fused dual-GEMM + bias + relu (layers 1 & 2) ----------------
// out[r, n0+j] = relu( sum_k A[r,k]*Wl[n0+j,k] + bias[n0+j] + sum_k H[r,k]*Wr[n0+j,k] )
// BM=128 x BN=64 tile, 256 threads, acc pairs over row-pairs (zero A packs).
__global__ __launch_bounds__(256, 3) void k_gemmJ(
    const float* __restrict__ A, const float* __restrict__ H,
    const float* __restrict__ Wl, const float* __restrict__ bias,
    const float* __restrict__ Wr, float* __restrict__ out)
{
    __shared__ float As[32][132];
    __shared__ float Ws[32][68];

    const int t    = threadIdx.x;
    const int ct   = t & 15;
    const int rt   = t >> 4;
    const int tn0  = ct * 4;
    const int tm0  = rt * 8;
    const int row0 = blockIdx.x * 128;
    const int n0   = blockIdx.y * 64;

    ull acc[4][4];
    #pragma unroll
    for (int mp = 0; mp < 4; mp++)
        #pragma unroll
        for (int j = 0; j < 4; j++) acc[mp][j] = 0ull;

    float4 areg[4];
    {
        #pragma unroll
        for (int i2 = 0; i2 < 4; i2++) {
            int li = t + i2 * 256, m = li >> 3, kq = li & 7, r = row0 + m;
            areg[i2] = (r < N_NODES) ? *(const float4*)(A + (size_t)r * 128 + kq * 4)
                                     : make_float4(0.f, 0.f, 0.f, 0.f);
        }
    }

    #pragma unroll 1
    for (int s = 0; s < 8; s++) {
        const int kc = (s & 3) * 32;
        const float* Wp = (s < 4) ? Wl : Wr;

        #pragma unroll
        for (int i2 = 0; i2 < 4; i2++) {
            int li = t + i2 * 256, m = li >> 3, kq = li & 7;
            As[kq * 4 + 0][m] = areg[i2].x;
            As[kq * 4 + 1][m] = areg[i2].y;
            As[kq * 4 + 2][m] = areg[i2].z;
            As[kq * 4 + 3][m] = areg[i2].w;
        }
        #pragma unroll
        for (int i2 = 0; i2 < 2; i2++) {
            int li = t + i2 * 256, j = li >> 3, kq = li & 7;
            float4 v = *(const float4*)(Wp + (size_t)(n0 + j) * 128 + kc + kq * 4);
            Ws[kq * 4 + 0][j] = v.x;
            Ws[kq * 4 + 1][j] = v.y;
            Ws[kq * 4 + 2][j] = v.z;
            Ws[kq * 4 + 3][j] = v.w;
        }
        __syncthreads();

        if (s < 7) {
            const float* Ap = ((s + 1) < 4) ? A : H;
            const int kcn = ((s + 1) & 3) * 32;
            #pragma unroll
            for (int i2 = 0; i2 < 4; i2++) {
                int li = t + i2 * 256, m = li >> 3, kq = li & 7, r = row0 + m;
                areg[i2] = (r < N_NODES) ? *(const float4*)(Ap + (size_t)r * 128 + kcn + kq * 4)
                                         : make_float4(0.f, 0.f, 0.f, 0.f);
            }
        }

        #pragma unroll
        for (int k = 0; k < 32; k++) {
            ulonglong2 ap01 = *(const ulonglong2*)&As[k][tm0];
            ulonglong2 ap23 = *(const ulonglong2*)&As[k][tm0 + 4];
            float4 w = *(const float4*)&Ws[k][tn0];
            ull w0 = pack2(w.x, w.x), w1 = pack2(w.y, w.y);
            ull w2 = pack2(w.z, w.z), w3 = pack2(w.w, w.w);
            fma2(acc[0][0], ap01.x, w0); fma2(acc[0][1], ap01.x, w1);
            fma2(acc[0][2], ap01.x, w2); fma2(acc[0][3], ap01.x, w3);
            fma2(acc[1][0], ap01.y, w0); fma2(acc[1][1], ap01.y, w1);
            fma2(acc[1][2], ap01.y, w2); fma2(acc[1][3], ap01.y, w3);
            fma2(acc[2][0], ap23.x, w0); fma2(acc[2][1], ap23.x, w1);
            fma2(acc[2][2], ap23.x, w2); fma2(acc[2][3], ap23.x, w3);
            fma2(acc[3][0], ap23.y, w0); fma2(acc[3][1], ap23.y, w1);
            fma2(acc[3][2], ap23.y, w2); fma2(acc[3][3], ap23.y, w3);
        }
        __syncthreads();
    }

    float4 bv = *(const float4*)(bias + n0 + tn0);
    #pragma unroll
    for (int mp = 0; mp < 4; mp++) {
        float2 c0 = unpack2(acc[mp][0]);
        float2 c1 = unpack2(acc[mp][1]);
        float2 c2 = unpack2(acc[mp][2]);
        float2 c3 = unpack2(acc[mp][3]);
        int r0 = row0 + tm0 + 2 * mp;
        int r1 = r0 + 1;
        if (r0 < N_NODES) {
            *(float4*)(out + (size_t)r0 * 128 + n0 + tn0) =
                make_float4(fmaxf(c0.x + bv.x, 0.f), fmaxf(c1.x + bv.y, 0.f),
                            fmaxf(c2.x + bv.z, 0.f), fmaxf(c3.x + bv.w, 0.f));
        }
        if (r1 < N_NODES) {
            *(float4*)(out + (size_t)r1 * 128 + n0 + tn0) =
                make_float4(fmaxf(c0.y + bv.x, 0.f), fmaxf(c1.y + bv.y, 0.f),
                            fmaxf(c2.y + bv.z, 0.f), fmaxf(c3.y + bv.w, 0.f));
        }
    }
}

// ---------------- layer-3 pair GEMM: p = H@Wl^T, q = H@Wr^T + bias ----------------
// BM=64 rows, J=32 cols, 256 threads, shared A tile for both outputs.
__global__ __launch_bounds__(256, 4) void k_gemm3(
    const float* __restrict__ H,
    const float* __restrict__ Wl, const float* __restrict__ bias,
    const float* __restrict__ Wr,
    float* __restrict__ p, float* __restrict__ q)
{
    __shared__ float As[32][68];
    __shared__ float Wls[32][36];
    __shared__ float Wrs[32][36];

    const int t    = threadIdx.x;
    const int ct   = t & 15;
    const int rt   = t >> 4;
    const int tn0  = ct * 2;
    const int tm0  = rt * 4;
    const int row0 = blockIdx.x * 64;

    ull accl[2][2], accr[2][2];
    #pragma unroll
    for (int mp = 0; mp < 2; mp++)
        #pragma unroll
        for (int j = 0; j < 2; j++) { accl[mp][j] = 0ull; accr[mp][j] = 0ull; }

    float4 areg[2];
    #pragma unroll
    for (int i2 = 0; i2 < 2; i2++) {
        int li = t + i2 * 256, m = li >> 3, kq = li & 7, r = row0 + m;
        areg[i2] = (r < N_NODES) ? *(const float4*)(H + (size_t)r * 128 + kq * 4)
                                 : make_float4(0.f, 0.f, 0.f, 0.f);
    }

    #pragma unroll 1
    for (int s = 0; s < 4; s++) {
        const int kc = s * 32;
        #pragma unroll
        for (int i2 = 0; i2 < 2; i2++) {
            int li = t + i2 * 256, m = li >> 3, kq = li & 7;
            As[kq * 4 + 0][m] = areg[i2].x;
            As[kq * 4 + 1][m] = areg[i2].y;
            As[kq * 4 + 2][m] = areg[i2].z;
            As[kq * 4 + 3][m] = areg[i2].w;
        }
        {
            int j = t >> 3, kq = t & 7;
            float4 vl = *(const float4*)(Wl + (size_t)j * 128 + kc + kq * 4);
            Wls[kq * 4 + 0][j] = vl.x; Wls[kq * 4 + 1][j] = vl.y;
            Wls[kq * 4 + 2][j] = vl.z; Wls[kq * 4 + 3][j] = vl.w;
            float4 vr = *(const float4*)(Wr + (size_t)j * 128 + kc + kq * 4);
            Wrs[kq * 4 + 0][j] = vr.x; Wrs[kq * 4 + 1][j] = vr.y;
            Wrs[kq * 4 + 2][j] = vr.z; Wrs[kq * 4 + 3][j] = vr.w;
        }
        __syncthreads();

        if (s < 3) {
            const int kcn = (s + 1) * 32;
            #pragma unroll
            for (int i2 = 0; i2 < 2; i2++) {
                int li = t + i2 * 256, m = li >> 3, kq = li & 7, r = row0 + m;
                areg[i2] = (r < N_NODES) ? *(const float4*)(H + (size_t)r * 128 + kcn + kq * 4)
                                         : make_float4(0.f, 0.f, 0.f, 0.f);
            }
        }

        #pragma unroll
        for (int k = 0; k < 32; k++) {
            ulonglong2 ap = *(const ulonglong2*)&As[k][tm0];
            float2 wl = *(const float2*)&Wls[k][tn0];
            float2 wr = *(const float2*)&Wrs[k][tn0];
            ull wl0 = pack2(wl.x, wl.x), wl1 = pack2(wl.y, wl.y);
            ull wr0 = pack2(wr.x, wr.x), wr1 = pack2(wr.y, wr.y);
            fma2(accl[0][0], ap.x, wl0); fma2(accl[0][1], ap.x, wl1);
            fma2(accl[1][0], ap.y, wl0); fma2(accl[1][1], ap.y, wl1);
            fma2(accr[0][0], ap.x, wr0); fma2(accr[0][1], ap.x, wr1);
            fma2(accr[1][0], ap.y, wr0); fma2(accr[1][1], ap.y, wr1);
        }
        __syncthreads();
    }

    float2 bv = *(const float2*)(bias + tn0);
    #pragma unroll
    for (int mp = 0; mp < 2; mp++) {
        float2 l0 = unpack2(accl[mp][0]);
        float2 l1 = unpack2(accl[mp][1]);
        float2 r0v = unpack2(accr[mp][0]);
        float2 r1v = unpack2(accr[mp][1]);
        int r0 = row0 + tm0 + 2 * mp;
        int r1 = r0 + 1;
        if (r0 < N_NODES) {
            *(float2*)(p + (size_t)r0 * 32 + tn0) = make_float2(l0.x, l1.x);
            *(float2*)(q + (size_t)r0 * 32 + tn0) = make_float2(r0v.x + bv.x, r1v.x + bv.y);
        }
        if (r1 < N_NODES) {
            *(float2*)(p + (size_t)r1 * 32 + tn0) = make_float2(l0.y, l1.y);
            *(float2*)(q + (size_t)r1 * 32 + tn0) = make_float2(r0v.y + bv.x, r1v.y + bv.y);
        }
    }
}

// ---------------- layer-3 aggregation in 32-d + final relu ----------------
__global__ void k_agg3(const float* __restrict__ p, const float* __restrict__ q,
                       float* __restrict__ out) {
    int w    = (blockIdx.x * blockDim.x + threadIdx.x) >> 5;
    int lane = threadIdx.x & 31;
    if (w >= N_NODES) return;

    int e  = g_off[w];
    int e1 = g_off[w + 1];
    float acc = 0.f;
    for (; e + 3 < e1; e += 4) {
        int s0 = g_srcs[e], s1 = g_srcs[e + 1], s2 = g_srcs[e + 2], s3 = g_srcs[e + 3];
        float v0 = p[(size_t)s0 * 32 + lane];
        float v1 = p[(size_t)s1 * 32 + lane];
        float v2 = p[(size_t)s2 * 32 + lane];
        float v3 = p[(size_t)s3 * 32 + lane];
        acc += (v0 + v1) + (v2 + v3);
    }
    for (; e < e1; e++) acc += p[(size_t)g_srcs[e] * 32 + lane];

    out[(size_t)w * 32 + lane] = fmaxf(acc * g_inv[w] + q[(size_t)w * 32 + lane], 0.f);
}

// ---------------- launch ----------------
extern "C" void kernel_launch(void* const* d_in, const int* in_sizes, int n_in,
                              void* d_out, int out_size) {
    const float* x   = (const float*)d_in[0];
    const int*   ei  = (const int*)d_in[1];
    const float* Wl1 = (const float*)d_in[2];
    const float* bl1 = (const float*)d_in[3];
    const float* Wr1 = (const float*)d_in[4];
    const float* Wl2 = (const float*)d_in[5];
    const float* bl2 = (const float*)d_in[6];
    const float* Wr2 = (const float*)d_in[7];
    const float* Wl3 = (const float*)d_in[8];
    const float* bl3 = (const float*)d_in[9];
    const float* Wr3 = (const float*)d_in[10];
    float* out = (float*)d_out;

    const int* src = ei;
    const int* dst = ei + N_EDGES;

    float *mean_p, *h1_p, *h2_p, *p_p, *q_p;
    cudaGetSymbolAddress((void**)&mean_p, g_mean);
    cudaGetSymbolAddress((void**)&h1_p,   g_h1);
    cudaGetSymbolAddress((void**)&h2_p,   g_h2);
    cudaGetSymbolAddress((void**)&p_p,    g_p);
    cudaGetSymbolAddress((void**)&q_p,    g_q);

    const int EB = (N_EDGES + 255) / 256;
    const int AB = (N_NODES * 32 + 255) / 256;
    dim3 GJ((N_NODES + 127) / 128, 2);
    const int G3 = (N_NODES + 63) / 64;

    // CSR build
    k_zero_deg<<<(N_NODES + 255) / 256, 256>>>();
    k_count<<<EB, 256>>>(dst);
    k_scan1<<<SCAN_B, 1024>>>();
    k_scan2<<<1, 64>>>();
    k_scan3<<<(N_NODES + 255) / 256, 256>>>();
    k_scatter<<<EB, 256>>>(src, dst);

    // layer 1
    k_agg<<<AB, 256>>>(x);
    k_gemmJ<<<GJ, 256>>>(mean_p, x, Wl1, bl1, Wr1, h1_p);
    // layer 2
    k_agg<<<AB, 256>>>(h1_p);
    k_gemmJ<<<GJ, 256>>>(mean_p, h1_p, Wl2, bl2, Wr2, h2_p);
    // layer 3: project to 32-d first, then aggregate in 32-d
    k_gemm3<<<G3, 256>>>(h2_p, Wl3, bl3, Wr3, p_p, q_p);
    k_agg3<<<AB, 256>>>(p_p, q_p, out);
}

// round 6
// speedup vs baseline: 1.5000x; 1.2078x over previous
#include <cuda_runtime.h>
#include <cuda_bf16.h>
#include <cstdint>

#define N_NODES 50000
#define N_EDGES 800000
#define SCAN_B  49   // ceil(50000/1024)

// ---------------- scratch (static __device__ globals; no allocation) ----------------
__device__ int   g_deg [N_NODES];
__device__ int   g_off [N_NODES + 1];
__device__ int   g_pos [N_NODES];
__device__ int   g_srcs[N_EDGES];
__device__ float g_inv [N_NODES];
__device__ int   g_bsum[64];
__device__ int   g_bpre[64];
__device__ float g_mean[(size_t)N_NODES * 128];
__device__ float g_h1  [(size_t)N_NODES * 128];
__device__ float g_h2  [(size_t)N_NODES * 128];
__device__ float g_p   [(size_t)N_NODES * 32];
__device__ float g_q   [(size_t)N_NODES * 32];

// ---------------- mma.sync helpers (plain sm_80+ PTX; no 'a'-gated features) ------
#define MMA_BF16(c, a, b) \
    asm volatile("mma.sync.aligned.m16n8k16.row.col.f32.bf16.bf16.f32 " \
        "{%0,%1,%2,%3}, {%4,%5,%6,%7}, {%8,%9}, {%0,%1,%2,%3};" \
        : "+f"((c)[0]), "+f"((c)[1]), "+f"((c)[2]), "+f"((c)[3]) \
        : "r"((a)[0]), "r"((a)[1]), "r"((a)[2]), "r"((a)[3]), \
          "r"((b)[0]), "r"((b)[1]))

__device__ __forceinline__ uint32_t pack_bf2(float a, float b) {
    __nv_bfloat162 h = __floats2bfloat162_rn(a, b);
    return *reinterpret_cast<uint32_t*>(&h);
}

// split float4 into bf16 hi pairs + bf16 lo pairs (packed as 2x uint32 each)
__device__ __forceinline__ void split_pack4(float4 v, uint2& hi, uint2& lo) {
    float hx = __bfloat162float(__float2bfloat16(v.x));
    float hy = __bfloat162float(__float2bfloat16(v.y));
    float hz = __bfloat162float(__float2bfloat16(v.z));
    float hw = __bfloat162float(__float2bfloat16(v.w));
    hi = make_uint2(pack_bf2(hx, hy), pack_bf2(hz, hw));
    lo = make_uint2(pack_bf2(v.x - hx, v.y - hy), pack_bf2(v.z - hz, v.w - hw));
}

// smem layout (bf16 elements), row stride 72 (=144B -> conflict-free frag loads)
#define A_STRIDE 72
#define SM_AH 0
#define SM_AL 9216       // 128*72
#define SM_WH 18432
#define SM_WL 23040      // + 64*72
#define SMEM_MMA ((23040 + 4608) * 2)   // 55296 bytes

// ---------------- CSR build ----------------
__global__ void k_count(const int* __restrict__ dst) {
    int e = blockIdx.x * blockDim.x + threadIdx.x;
    if (e < N_EDGES) atomicAdd(&g_deg[dst[e]], 1);
}

__global__ void k_scan1() {
    __shared__ int wsum[32];
    int t = threadIdx.x, b = blockIdx.x;
    int i = b * 1024 + t;
    int v = (i < N_NODES) ? g_deg[i] : 0;
    int lane = t & 31, w = t >> 5;
    int x = v;
    #pragma unroll
    for (int o = 1; o < 32; o <<= 1) {
        int y = __shfl_up_sync(0xffffffffu, x, o);
        if (lane >= o) x += y;
    }
    if (lane == 31) wsum[w] = x;
    __syncthreads();
    if (w == 0) {
        int s = wsum[lane];
        #pragma unroll
        for (int o = 1; o < 32; o <<= 1) {
            int y = __shfl_up_sync(0xffffffffu, s, o);
            if (lane >= o) s += y;
        }
        wsum[lane] = s;
    }
    __syncthreads();
    int incl = x + (w > 0 ? wsum[w - 1] : 0);
    if (i < N_NODES) {
        g_off[i + 1] = incl;
        g_inv[i] = (v > 0) ? (1.0f / (float)v) : 0.0f;
    }
    if (t == 1023) g_bsum[b] = incl;
}

__global__ void k_scan2() {
    __shared__ int buf[2];
    int t = threadIdx.x;
    if (t < 2) buf[t] = 0;
    __syncthreads();
    int v = (t < SCAN_B) ? g_bsum[t] : 0;
    int lane = t & 31, w = t >> 5;
    int x = v;
    #pragma unroll
    for (int o = 1; o < 32; o <<= 1) {
        int y = __shfl_up_sync(0xffffffffu, x, o);
        if (lane >= o) x += y;
    }
    if (lane == 31) buf[w] = x;
    __syncthreads();
    if (w == 1) x += buf[0];
    if (t < SCAN_B) g_bpre[t] = x - v;
}

__global__ void k_scan3() {
    int i = blockIdx.x * blockDim.x + threadIdx.x;
    if (i < N_NODES) {
        int o = g_off[i + 1] + g_bpre[i >> 10];
        g_off[i + 1] = o;
        g_pos[i] = o - g_deg[i];
    }
    if (i == 0) g_off[0] = 0;
}

__global__ void k_scatter(const int* __restrict__ src, const int* __restrict__ dst) {
    int e = blockIdx.x * blockDim.x + threadIdx.x;
    if (e < N_EDGES) {
        int d = dst[e];
        int p = atomicAdd(&g_pos[d], 1);
        g_srcs[p] = src[e];
    }
}

// ---------------- mean aggregation (128-d): one warp per node ----------------
__global__ void k_agg(const float* __restrict__ h) {
    int w    = (blockIdx.x * blockDim.x + threadIdx.x) >> 5;
    int lane = threadIdx.x & 31;
    if (w >= N_NODES) return;

    int e  = g_off[w];
    int e1 = g_off[w + 1];
    float4 acc = make_float4(0.f, 0.f, 0.f, 0.f);
    const float* base = h + lane * 4;

    for (; e + 3 < e1; e += 4) {
        int s0 = g_srcs[e], s1 = g_srcs[e + 1], s2 = g_srcs[e + 2], s3 = g_srcs[e + 3];
        float4 v0 = *(const float4*)(base + (size_t)s0 * 128);
        float4 v1 = *(const float4*)(base + (size_t)s1 * 128);
        float4 v2 = *(const float4*)(base + (size_t)s2 * 128);
        float4 v3 = *(const float4*)(base + (size_t)s3 * 128);
        acc.x += (v0.x + v1.x) + (v2.x + v3.x);
        acc.y += (v0.y + v1.y) + (v2.y + v3.y);
        acc.z += (v0.z + v1.z) + (v2.z + v3.z);
        acc.w += (v0.w + v1.w) + (v2.w + v3.w);
    }
    for (; e < e1; e++) {
        int s = g_srcs[e];
        float4 v = *(const float4*)(base + (size_t)s * 128);
        acc.x += v.x; acc.y += v.y; acc.z += v.z; acc.w += v.w;
    }

    float inv = g_inv[w];
    *(float4*)(g_mean + (size_t)w * 128 + lane * 4) =
        make_float4(acc.x * inv, acc.y * inv, acc.z * inv, acc.w * inv);
}

// ---------------- shared device routines for the mma GEMMs ----------------
// Load + bf16x2-split a 128x64 A chunk into smem [m][k] (stride 72).
__device__ __forceinline__ void load_A_chunk(
    __nv_bfloat16* smb, const float* __restrict__ Ap, int row0, int kc, int t)
{
    int m = t >> 1, kh = (t & 1) * 32;
    int r = row0 + m;
    bool ok = (r < N_NODES);
    const float* gsrc = Ap + (size_t)r * 128 + kc + kh;
    #pragma unroll
    for (int i = 0; i < 8; i++) {
        float4 v = ok ? *(const float4*)(gsrc + i * 4)
                      : make_float4(0.f, 0.f, 0.f, 0.f);
        uint2 hi, lo;
        split_pack4(v, hi, lo);
        int off = m * A_STRIDE + kh + i * 4;
        *(uint2*)(smb + SM_AH + off) = hi;
        *(uint2*)(smb + SM_AL + off) = lo;
    }
}

// Load + split a 64x64 W chunk into smem [j][k] (stride 72).
__device__ __forceinline__ void load_W_chunk(
    __nv_bfloat16* smb, const float* __restrict__ wrow, int kc, int t)
{
    int kh = (t & 3) * 16;
    #pragma unroll
    for (int i = 0; i < 4; i++) {
        float4 v = *(const float4*)(wrow + kc + kh + i * 4);
        uint2 hi, lo;
        split_pack4(v, hi, lo);
        int off = (t >> 2) * A_STRIDE + kh + i * 4;
        *(uint2*)(smb + SM_WH + off) = hi;
        *(uint2*)(smb + SM_WL + off) = lo;
    }
}

// Compute one K=64 chunk: 4 k-frags x (2 m-tiles x 4 n-tiles) x 3 split terms.
__device__ __forceinline__ void mma_chunk(
    const __nv_bfloat16* smb, int wm, int wn, int lane, float c[2][4][4])
{
    #pragma unroll
    for (int kf = 0; kf < 4; kf++) {
        int kcol = kf * 16 + (lane & 3) * 2;
        uint32_t ah[2][4], al[2][4];
        #pragma unroll
        for (int mt = 0; mt < 2; mt++) {
            int base = (wm * 32 + mt * 16 + (lane >> 2)) * A_STRIDE + kcol;
            ah[mt][0] = *(const uint32_t*)(smb + SM_AH + base);
            ah[mt][1] = *(const uint32_t*)(smb + SM_AH + base + 8 * A_STRIDE);
            ah[mt][2] = *(const uint32_t*)(smb + SM_AH + base + 8);
            ah[mt][3] = *(const uint32_t*)(smb + SM_AH + base + 8 * A_STRIDE + 8);
            al[mt][0] = *(const uint32_t*)(smb + SM_AL + base);
            al[mt][1] = *(const uint32_t*)(smb + SM_AL + base + 8 * A_STRIDE);
            al[mt][2] = *(const uint32_t*)(smb + SM_AL + base + 8);
            al[mt][3] = *(const uint32_t*)(smb + SM_AL + base + 8 * A_STRIDE + 8);
        }
        uint32_t bh[4][2], bl[4][2];
        #pragma unroll
        for (int nt = 0; nt < 4; nt++) {
            int base = (wn * 32 + nt * 8 + (lane >> 2)) * A_STRIDE + kcol;
            bh[nt][0] = *(const uint32_t*)(smb + SM_WH + base);
            bh[nt][1] = *(const uint32_t*)(smb + SM_WH + base + 8);
            bl[nt][0] = *(const uint32_t*)(smb + SM_WL + base);
            bl[nt][1] = *(const uint32_t*)(smb + SM_WL + base + 8);
        }
        #pragma unroll
        for (int mt = 0; mt < 2; mt++)
            #pragma unroll
            for (int nt = 0; nt < 4; nt++) {
                MMA_BF16(c[mt][nt], ah[mt], bh[nt]);
                MMA_BF16(c[mt][nt], al[mt], bh[nt]);
                MMA_BF16(c[mt][nt], ah[mt], bl[nt]);
            }
    }
}

// ---------------- dual GEMM + bias + relu (layers 1 & 2), bf16x3 mma.sync -------
// out[r, n0+j] = relu( sum_k A[r,k]*Wl[n0+j,k] + bias[n0+j] + sum_k H[r,k]*Wr[n0+j,k] )
__global__ __launch_bounds__(256) void k_gemmJ_mma(
    const float* __restrict__ A, const float* __restrict__ H,
    const float* __restrict__ Wl, const float* __restrict__ bias,
    const float* __restrict__ Wr, float* __restrict__ out)
{
    extern __shared__ __nv_bfloat16 smb[];
    const int t    = threadIdx.x;
    const int lane = t & 31;
    const int w    = t >> 5;
    const int wm   = w & 3;       // M group (32 rows)
    const int wn   = w >> 2;      // N group (32 cols)
    const int row0 = blockIdx.x * 128;
    const int n0   = blockIdx.y * 64;

    float c[2][4][4];
    #pragma unroll
    for (int mt = 0; mt < 2; mt++)
        #pragma unroll
        for (int nt = 0; nt < 4; nt++)
            #pragma unroll
            for (int i = 0; i < 4; i++) c[mt][nt][i] = 0.f;

    #pragma unroll 1
    for (int ph = 0; ph < 2; ph++) {
        const float* Ap = ph ? H  : A;
        const float* Wp = ph ? Wr : Wl;
        #pragma unroll 1
        for (int ck = 0; ck < 2; ck++) {
            const int kc = ck * 64;
            load_A_chunk(smb, Ap, row0, kc, t);
            load_W_chunk(smb, Wp + (size_t)(n0 + (t >> 2)) * 128, kc, t);
            __syncthreads();
            mma_chunk(smb, wm, wn, lane, c);
            __syncthreads();
        }
    }

    // epilogue: bias + relu
    #pragma unroll
    for (int mt = 0; mt < 2; mt++) {
        int r0 = row0 + wm * 32 + mt * 16 + (lane >> 2);
        #pragma unroll
        for (int nt = 0; nt < 4; nt++) {
            int col = n0 + wn * 32 + nt * 8 + (lane & 3) * 2;
            float b0 = bias[col], b1 = bias[col + 1];
            if (r0 < N_NODES)
                *(float2*)(out + (size_t)r0 * 128 + col) = make_float2(
                    fmaxf(c[mt][nt][0] + b0, 0.f), fmaxf(c[mt][nt][1] + b1, 0.f));
            if (r0 + 8 < N_NODES)
                *(float2*)(out + (size_t)(r0 + 8) * 128 + col) = make_float2(
                    fmaxf(c[mt][nt][2] + b0, 0.f), fmaxf(c[mt][nt][3] + b1, 0.f));
        }
    }
}

// ---------------- layer-3 pair GEMM: p = H@Wl3^T, q = H@Wr3^T + b (N=64 stacked) --
__global__ __launch_bounds__(256) void k_gemm3_mma(
    const float* __restrict__ H,
    const float* __restrict__ Wl, const float* __restrict__ bias,
    const float* __restrict__ Wr,
    float* __restrict__ p, float* __restrict__ q)
{
    extern __shared__ __nv_bfloat16 smb[];
    const int t    = threadIdx.x;
    const int lane = t & 31;
    const int w    = t >> 5;
    const int wm   = w & 3;
    const int wn   = w >> 2;      // 0 -> p (Wl cols), 1 -> q (Wr cols)
    const int row0 = blockIdx.x * 128;

    float c[2][4][4];
    #pragma unroll
    for (int mt = 0; mt < 2; mt++)
        #pragma unroll
        for (int nt = 0; nt < 4; nt++)
            #pragma unroll
            for (int i = 0; i < 4; i++) c[mt][nt][i] = 0.f;

    #pragma unroll 1
    for (int ck = 0; ck < 2; ck++) {
        const int kc = ck * 64;
        load_A_chunk(smb, H, row0, kc, t);
        {
            int j = t >> 2;
            const float* wrow = (j < 32) ? (Wl + (size_t)j * 128)
                                         : (Wr + (size_t)(j - 32) * 128);
            load_W_chunk(smb, wrow, kc, t);
        }
        __syncthreads();
        mma_chunk(smb, wm, wn, lane, c);
        __syncthreads();
    }

    float* dstm = (wn == 0) ? p : q;
    #pragma unroll
    for (int mt = 0; mt < 2; mt++) {
        int r0 = row0 + wm * 32 + mt * 16 + (lane >> 2);
        #pragma unroll
        for (int nt = 0; nt < 4; nt++) {
            int col = nt * 8 + (lane & 3) * 2;   // 0..31 within p or q
            float b0 = (wn == 1) ? bias[col]     : 0.f;
            float b1 = (wn == 1) ? bias[col + 1] : 0.f;
            if (r0 < N_NODES)
                *(float2*)(dstm + (size_t)r0 * 32 + col) =
                    make_float2(c[mt][nt][0] + b0, c[mt][nt][1] + b1);
            if (r0 + 8 < N_NODES)
                *(float2*)(dstm + (size_t)(r0 + 8) * 32 + col) =
                    make_float2(c[mt][nt][2] + b0, c[mt][nt][3] + b1);
        }
    }
}

// ---------------- layer-3 aggregation in 32-d + final relu ----------------
__global__ void k_agg3(const float* __restrict__ p, const float* __restrict__ q,
                       float* __restrict__ out) {
    int w    = (blockIdx.x * blockDim.x + threadIdx.x) >> 5;
    int lane = threadIdx.x & 31;
    if (w >= N_NODES) return;

    int e  = g_off[w];
    int e1 = g_off[w + 1];
    float acc = 0.f;
    for (; e + 3 < e1; e += 4) {
        int s0 = g_srcs[e], s1 = g_srcs[e + 1], s2 = g_srcs[e + 2], s3 = g_srcs[e + 3];
        float v0 = p[(size_t)s0 * 32 + lane];
        float v1 = p[(size_t)s1 * 32 + lane];
        float v2 = p[(size_t)s2 * 32 + lane];
        float v3 = p[(size_t)s3 * 32 + lane];
        acc += (v0 + v1) + (v2 + v3);
    }
    for (; e < e1; e++) acc += p[(size_t)g_srcs[e] * 32 + lane];

    out[(size_t)w * 32 + lane] = fmaxf(acc * g_inv[w] + q[(size_t)w * 32 + lane], 0.f);
}

// ---------------- launch ----------------
extern "C" void kernel_launch(void* const* d_in, const int* in_sizes, int n_in,
                              void* d_out, int out_size) {
    const float* x   = (const float*)d_in[0];
    const int*   ei  = (const int*)d_in[1];
    const float* Wl1 = (const float*)d_in[2];
    const float* bl1 = (const float*)d_in[3];
    const float* Wr1 = (const float*)d_in[4];
    const float* Wl2 = (const float*)d_in[5];
    const float* bl2 = (const float*)d_in[6];
    const float* Wr2 = (const float*)d_in[7];
    const float* Wl3 = (const float*)d_in[8];
    const float* bl3 = (const float*)d_in[9];
    const float* Wr3 = (const float*)d_in[10];
    float* out = (float*)d_out;

    const int* src = ei;
    const int* dst = ei + N_EDGES;

    cudaFuncSetAttribute(k_gemmJ_mma, cudaFuncAttributeMaxDynamicSharedMemorySize, SMEM_MMA);
    cudaFuncSetAttribute(k_gemm3_mma, cudaFuncAttributeMaxDynamicSharedMemorySize, SMEM_MMA);

    int* deg_p;
    float *mean_p, *h1_p, *h2_p, *p_p, *q_p;
    cudaGetSymbolAddress((void**)&deg_p,  g_deg);
    cudaGetSymbolAddress((void**)&mean_p, g_mean);
    cudaGetSymbolAddress((void**)&h1_p,   g_h1);
    cudaGetSymbolAddress((void**)&h2_p,   g_h2);
    cudaGetSymbolAddress((void**)&p_p,    g_p);
    cudaGetSymbolAddress((void**)&q_p,    g_q);

    const int EB = (N_EDGES + 255) / 256;
    const int AB = (N_NODES * 32 + 255) / 256;
    dim3 GJ((N_NODES + 127) / 128, 2);
    const int G3 = (N_NODES + 127) / 128;

    // CSR build
    cudaMemsetAsync(deg_p, 0, N_NODES * sizeof(int));
    k_count<<<EB, 256>>>(dst);
    k_scan1<<<SCAN_B, 1024>>>();
    k_scan2<<<1, 64>>>();
    k_scan3<<<(N_NODES + 255) / 256, 256>>>();
    k_scatter<<<EB, 256>>>(src, dst);

    // layer 1
    k_agg<<<AB, 256>>>(x);
    k_gemmJ_mma<<<GJ, 256, SMEM_MMA>>>(mean_p, x, Wl1, bl1, Wr1, h1_p);
    // layer 2
    k_agg<<<AB, 256>>>(h1_p);
    k_gemmJ_mma<<<GJ, 256, SMEM_MMA>>>(mean_p, h1_p, Wl2, bl2, Wr2, h2_p);
    // layer 3: project to 32-d first (p,q in one N=64 GEMM), aggregate in 32-d
    k_gemm3_mma<<<G3, 256, SMEM_MMA>>>(h2_p, Wl3, bl3, Wr3, p_p, q_p);
    k_agg3<<<AB, 256>>>(p_p, q_p, out);
}

// round 7
// speedup vs baseline: 1.6258x; 1.0839x over previous
#include <cuda_runtime.h>
#include <cuda_bf16.h>
#include <cstdint>

#define N_NODES 50000
#define N_EDGES 800000
#define SCAN_B  49   // ceil(50000/1024)

// ---------------- scratch (static __device__ globals; no allocation) ----------------
__device__ int   g_deg [N_NODES];
__device__ int   g_off [N_NODES + 1];
__device__ int   g_pos [N_NODES];
__device__ int   g_srcs[N_EDGES];
__device__ float g_inv [N_NODES];
__device__ int   g_bsum[64];
__device__ int   g_bpre[64];

__device__ float g_h1 [(size_t)N_NODES * 128];   // fp32 (gathered by agg2)
__device__ float g_p  [(size_t)N_NODES * 32];
__device__ float g_q  [(size_t)N_NODES * 32];

// bf16 hi/lo planes (pre-split operands for mma GEMMs)
__device__ __align__(16) __nv_bfloat16 g_xh [(size_t)N_NODES * 128];
__device__ __align__(16) __nv_bfloat16 g_xl [(size_t)N_NODES * 128];
__device__ __align__(16) __nv_bfloat16 g_mh [(size_t)N_NODES * 128];
__device__ __align__(16) __nv_bfloat16 g_ml [(size_t)N_NODES * 128];
__device__ __align__(16) __nv_bfloat16 g_h1h[(size_t)N_NODES * 128];
__device__ __align__(16) __nv_bfloat16 g_h1l[(size_t)N_NODES * 128];
__device__ __align__(16) __nv_bfloat16 g_h2h[(size_t)N_NODES * 128];
__device__ __align__(16) __nv_bfloat16 g_h2l[(size_t)N_NODES * 128];
// packed W planes: rows [0,128)=Wl1, [128,256)=Wr1, [256,384)=Wl2, [384,512)=Wr2,
//                  [512,544)=Wl3, [544,576)=Wr3
#define WROWS 576
__device__ __align__(16) __nv_bfloat16 g_wh[WROWS * 128];
__device__ __align__(16) __nv_bfloat16 g_wl[WROWS * 128];

// ---------------- helpers ----------------
#define MMA_BF16(c, a, b) \
    asm volatile("mma.sync.aligned.m16n8k16.row.col.f32.bf16.bf16.f32 " \
        "{%0,%1,%2,%3}, {%4,%5,%6,%7}, {%8,%9}, {%0,%1,%2,%3};" \
        : "+f"((c)[0]), "+f"((c)[1]), "+f"((c)[2]), "+f"((c)[3]) \
        : "r"((a)[0]), "r"((a)[1]), "r"((a)[2]), "r"((a)[3]), \
          "r"((b)[0]), "r"((b)[1]))

__device__ __forceinline__ uint32_t pack_bf2(float a, float b) {
    __nv_bfloat162 h = __floats2bfloat162_rn(a, b);
    return *reinterpret_cast<uint32_t*>(&h);
}
__device__ __forceinline__ void split_pack4(float4 v, uint2& hi, uint2& lo) {
    float hx = __bfloat162float(__float2bfloat16(v.x));
    float hy = __bfloat162float(__float2bfloat16(v.y));
    float hz = __bfloat162float(__float2bfloat16(v.z));
    float hw = __bfloat162float(__float2bfloat16(v.w));
    hi = make_uint2(pack_bf2(hx, hy), pack_bf2(hz, hw));
    lo = make_uint2(pack_bf2(v.x - hx, v.y - hy), pack_bf2(v.z - hz, v.w - hw));
}
__device__ __forceinline__ void split2(float f0, float f1, uint32_t& hi, uint32_t& lo) {
    float h0 = __bfloat162float(__float2bfloat16(f0));
    float h1 = __bfloat162float(__float2bfloat16(f1));
    hi = pack_bf2(h0, h1);
    lo = pack_bf2(f0 - h0, f1 - h1);
}

// smem layout (bf16 elements), row stride 72 (144B, 16B-aligned, conflict-free frags)
#define A_STRIDE 72
#define SM_AH 0
#define SM_AL 9216       // 128*72
#define SM_WH 18432
#define SM_WL 23040
#define SMEM_MMA ((23040 + 4608) * 2)   // 55296 bytes

// ---------------- one-shot split: x + packed W -> bf16 hi/lo planes ----------------
#define X4 1600000          // 50000*128/4
#define W4 18432            // 576*128/4
__global__ void k_split(const float* __restrict__ x,
                        const float* __restrict__ Wl1, const float* __restrict__ Wr1,
                        const float* __restrict__ Wl2, const float* __restrict__ Wr2,
                        const float* __restrict__ Wl3, const float* __restrict__ Wr3) {
    int i = blockIdx.x * blockDim.x + threadIdx.x;
    if (i < X4) {
        float4 v = *(const float4*)(x + (size_t)i * 4);
        uint2 hi, lo; split_pack4(v, hi, lo);
        *(uint2*)(g_xh + (size_t)i * 4) = hi;
        *(uint2*)(g_xl + (size_t)i * 4) = lo;
    } else if (i < X4 + W4) {
        int wi = i - X4;
        int row = wi >> 5, c4 = wi & 31;
        const float* src;
        if      (row < 128) src = Wl1 + (size_t)row * 128;
        else if (row < 256) src = Wr1 + (size_t)(row - 128) * 128;
        else if (row < 384) src = Wl2 + (size_t)(row - 256) * 128;
        else if (row < 512) src = Wr2 + (size_t)(row - 384) * 128;
        else if (row < 544) src = Wl3 + (size_t)(row - 512) * 128;
        else                src = Wr3 + (size_t)(row - 544) * 128;
        float4 v = *(const float4*)(src + c4 * 4);
        uint2 hi, lo; split_pack4(v, hi, lo);
        *(uint2*)(g_wh + row * 128 + c4 * 4) = hi;
        *(uint2*)(g_wl + row * 128 + c4 * 4) = lo;
    }
}

// ---------------- CSR build ----------------
__global__ void k_count(const int* __restrict__ dst) {
    int e = blockIdx.x * blockDim.x + threadIdx.x;
    if (e < N_EDGES) atomicAdd(&g_deg[dst[e]], 1);
}

__global__ void k_scan1() {
    __shared__ int wsum[32];
    int t = threadIdx.x, b = blockIdx.x;
    int i = b * 1024 + t;
    int v = (i < N_NODES) ? g_deg[i] : 0;
    int lane = t & 31, w = t >> 5;
    int x = v;
    #pragma unroll
    for (int o = 1; o < 32; o <<= 1) {
        int y = __shfl_up_sync(0xffffffffu, x, o);
        if (lane >= o) x += y;
    }
    if (lane == 31) wsum[w] = x;
    __syncthreads();
    if (w == 0) {
        int s = wsum[lane];
        #pragma unroll
        for (int o = 1; o < 32; o <<= 1) {
            int y = __shfl_up_sync(0xffffffffu, s, o);
            if (lane >= o) s += y;
        }
        wsum[lane] = s;
    }
    __syncthreads();
    int incl = x + (w > 0 ? wsum[w - 1] : 0);
    if (i < N_NODES) {
        g_off[i + 1] = incl;
        g_inv[i] = (v > 0) ? (1.0f / (float)v) : 0.0f;
    }
    if (t == 1023) g_bsum[b] = incl;
}

__global__ void k_scan2() {
    __shared__ int buf[2];
    int t = threadIdx.x;
    if (t < 2) buf[t] = 0;
    __syncthreads();
    int v = (t < SCAN_B) ? g_bsum[t] : 0;
    int lane = t & 31, w = t >> 5;
    int x = v;
    #pragma unroll
    for (int o = 1; o < 32; o <<= 1) {
        int y = __shfl_up_sync(0xffffffffu, x, o);
        if (lane >= o) x += y;
    }
    if (lane == 31) buf[w] = x;
    __syncthreads();
    if (w == 1) x += buf[0];
    if (t < SCAN_B) g_bpre[t] = x - v;
}

__global__ void k_scan3() {
    int i = blockIdx.x * blockDim.x + threadIdx.x;
    if (i < N_NODES) {
        int o = g_off[i + 1] + g_bpre[i >> 10];
        g_off[i + 1] = o;
        g_pos[i] = o - g_deg[i];
    }
    if (i == 0) g_off[0] = 0;
}

__global__ void k_scatter(const int* __restrict__ src, const int* __restrict__ dst) {
    int e = blockIdx.x * blockDim.x + threadIdx.x;
    if (e < N_EDGES) {
        int d = dst[e];
        int p = atomicAdd(&g_pos[d], 1);
        g_srcs[p] = src[e];
    }
}

// ------- mean aggregation (128-d): warp/node; emits mean as bf16 hi/lo planes -------
__global__ void k_agg(const float* __restrict__ h) {
    int w    = (blockIdx.x * blockDim.x + threadIdx.x) >> 5;
    int lane = threadIdx.x & 31;
    if (w >= N_NODES) return;

    int e  = g_off[w];
    int e1 = g_off[w + 1];
    float4 acc = make_float4(0.f, 0.f, 0.f, 0.f);
    const float* base = h + lane * 4;

    for (; e + 3 < e1; e += 4) {
        int s0 = g_srcs[e], s1 = g_srcs[e + 1], s2 = g_srcs[e + 2], s3 = g_srcs[e + 3];
        float4 v0 = *(const float4*)(base + (size_t)s0 * 128);
        float4 v1 = *(const float4*)(base + (size_t)s1 * 128);
        float4 v2 = *(const float4*)(base + (size_t)s2 * 128);
        float4 v3 = *(const float4*)(base + (size_t)s3 * 128);
        acc.x += (v0.x + v1.x) + (v2.x + v3.x);
        acc.y += (v0.y + v1.y) + (v2.y + v3.y);
        acc.z += (v0.z + v1.z) + (v2.z + v3.z);
        acc.w += (v0.w + v1.w) + (v2.w + v3.w);
    }
    for (; e < e1; e++) {
        int s = g_srcs[e];
        float4 v = *(const float4*)(base + (size_t)s * 128);
        acc.x += v.x; acc.y += v.y; acc.z += v.z; acc.w += v.w;
    }

    float inv = g_inv[w];
    float4 o = make_float4(acc.x * inv, acc.y * inv, acc.z * inv, acc.w * inv);
    uint2 hi, lo; split_pack4(o, hi, lo);
    *(uint2*)(g_mh + (size_t)w * 128 + lane * 4) = hi;
    *(uint2*)(g_ml + (size_t)w * 128 + lane * 4) = lo;
}

// ---------------- plane -> smem copies ----------------
__device__ __forceinline__ void load_A_plane(
    __nv_bfloat16* smb, const __nv_bfloat16* __restrict__ ph,
    const __nv_bfloat16* __restrict__ pl, int row0, int kc, int t)
{
    int m = t >> 1, kh = (t & 1) * 32;
    int r = row0 + m;
    int off = m * A_STRIDE + kh;
    if (r < N_NODES) {
        const uint4* gh = (const uint4*)(ph + (size_t)r * 128 + kc + kh);
        const uint4* gl = (const uint4*)(pl + (size_t)r * 128 + kc + kh);
        #pragma unroll
        for (int i = 0; i < 4; i++) {
            *(uint4*)(smb + SM_AH + off + i * 8) = gh[i];
            *(uint4*)(smb + SM_AL + off + i * 8) = gl[i];
        }
    } else {
        uint4 z = make_uint4(0, 0, 0, 0);
        #pragma unroll
        for (int i = 0; i < 4; i++) {
            *(uint4*)(smb + SM_AH + off + i * 8) = z;
            *(uint4*)(smb + SM_AL + off + i * 8) = z;
        }
    }
}

// W plane chunk: 64 output-cols x 64 k. wrow0 = packed W base row (+ n0 folded in).
__device__ __forceinline__ void load_W_plane(
    __nv_bfloat16* smb, int wrow0, int kc, int t)
{
    int j = t >> 2, kh = (t & 3) * 16;
    int off = j * A_STRIDE + kh;
    const uint4* gh = (const uint4*)(g_wh + (size_t)(wrow0 + j) * 128 + kc + kh);
    const uint4* gl = (const uint4*)(g_wl + (size_t)(wrow0 + j) * 128 + kc + kh);
    #pragma unroll
    for (int i = 0; i < 2; i++) {
        *(uint4*)(smb + SM_WH + off + i * 8) = gh[i];
        *(uint4*)(smb + SM_WL + off + i * 8) = gl[i];
    }
}

// one K=64 chunk of bf16x3 mma
__device__ __forceinline__ void mma_chunk(
    const __nv_bfloat16* smb, int wm, int wn, int lane, float c[2][4][4])
{
    #pragma unroll
    for (int kf = 0; kf < 4; kf++) {
        int kcol = kf * 16 + (lane & 3) * 2;
        uint32_t ah[2][4], al[2][4];
        #pragma unroll
        for (int mt = 0; mt < 2; mt++) {
            int base = (wm * 32 + mt * 16 + (lane >> 2)) * A_STRIDE + kcol;
            ah[mt][0] = *(const uint32_t*)(smb + SM_AH + base);
            ah[mt][1] = *(const uint32_t*)(smb + SM_AH + base + 8 * A_STRIDE);
            ah[mt][2] = *(const uint32_t*)(smb + SM_AH + base + 8);
            ah[mt][3] = *(const uint32_t*)(smb + SM_AH + base + 8 * A_STRIDE + 8);
            al[mt][0] = *(const uint32_t*)(smb + SM_AL + base);
            al[mt][1] = *(const uint32_t*)(smb + SM_AL + base + 8 * A_STRIDE);
            al[mt][2] = *(const uint32_t*)(smb + SM_AL + base + 8);
            al[mt][3] = *(const uint32_t*)(smb + SM_AL + base + 8 * A_STRIDE + 8);
        }
        uint32_t bh[4][2], bl[4][2];
        #pragma unroll
        for (int nt = 0; nt < 4; nt++) {
            int base = (wn * 32 + nt * 8 + (lane >> 2)) * A_STRIDE + kcol;
            bh[nt][0] = *(const uint32_t*)(smb + SM_WH + base);
            bh[nt][1] = *(const uint32_t*)(smb + SM_WH + base + 8);
            bl[nt][0] = *(const uint32_t*)(smb + SM_WL + base);
            bl[nt][1] = *(const uint32_t*)(smb + SM_WL + base + 8);
        }
        #pragma unroll
        for (int mt = 0; mt < 2; mt++)
            #pragma unroll
            for (int nt = 0; nt < 4; nt++) {
                MMA_BF16(c[mt][nt], ah[mt], bh[nt]);
                MMA_BF16(c[mt][nt], al[mt], bh[nt]);
                MMA_BF16(c[mt][nt], ah[mt], bl[nt]);
            }
    }
}

// ---------- dual GEMM + bias + relu (layers 1 & 2), pre-split plane operands -------
// out = relu(mean @ Wl^T + b + root @ Wr^T); writes fp32 (optional) + bf16 planes
template <bool WRITE_F32>
__global__ __launch_bounds__(256) void k_gemmJ_mma(
    const __nv_bfloat16* __restrict__ mh, const __nv_bfloat16* __restrict__ ml,
    const __nv_bfloat16* __restrict__ rh, const __nv_bfloat16* __restrict__ rl,
    int wl_row, int wr_row, const float* __restrict__ bias,
    float* __restrict__ outf,
    __nv_bfloat16* __restrict__ outh, __nv_bfloat16* __restrict__ outl)
{
    extern __shared__ __nv_bfloat16 smb[];
    const int t    = threadIdx.x;
    const int lane = t & 31;
    const int w    = t >> 5;
    const int wm   = w & 3;
    const int wn   = w >> 2;
    const int row0 = blockIdx.x * 128;
    const int n0   = blockIdx.y * 64;

    float c[2][4][4];
    #pragma unroll
    for (int mt = 0; mt < 2; mt++)
        #pragma unroll
        for (int nt = 0; nt < 4; nt++)
            #pragma unroll
            for (int i = 0; i < 4; i++) c[mt][nt][i] = 0.f;

    #pragma unroll 1
    for (int ph = 0; ph < 2; ph++) {
        const __nv_bfloat16* ahp = ph ? rh : mh;
        const __nv_bfloat16* alp = ph ? rl : ml;
        const int wr0 = (ph ? wr_row : wl_row) + n0;
        #pragma unroll 1
        for (int ck = 0; ck < 2; ck++) {
            const int kc = ck * 64;
            load_A_plane(smb, ahp, alp, row0, kc, t);
            load_W_plane(smb, wr0, kc, t);
            __syncthreads();
            mma_chunk(smb, wm, wn, lane, c);
            __syncthreads();
        }
    }

    #pragma unroll
    for (int mt = 0; mt < 2; mt++) {
        int r0 = row0 + wm * 32 + mt * 16 + (lane >> 2);
        #pragma unroll
        for (int nt = 0; nt < 4; nt++) {
            int col = n0 + wn * 32 + nt * 8 + (lane & 3) * 2;
            float b0 = bias[col], b1 = bias[col + 1];
            if (r0 < N_NODES) {
                float f0 = fmaxf(c[mt][nt][0] + b0, 0.f);
                float f1 = fmaxf(c[mt][nt][1] + b1, 0.f);
                if (WRITE_F32)
                    *(float2*)(outf + (size_t)r0 * 128 + col) = make_float2(f0, f1);
                uint32_t hi, lo; split2(f0, f1, hi, lo);
                *(uint32_t*)(outh + (size_t)r0 * 128 + col) = hi;
                *(uint32_t*)(outl + (size_t)r0 * 128 + col) = lo;
            }
            if (r0 + 8 < N_NODES) {
                float f2 = fmaxf(c[mt][nt][2] + b0, 0.f);
                float f3 = fmaxf(c[mt][nt][3] + b1, 0.f);
                if (WRITE_F32)
                    *(float2*)(outf + (size_t)(r0 + 8) * 128 + col) = make_float2(f2, f3);
                uint32_t hi, lo; split2(f2, f3, hi, lo);
                *(uint32_t*)(outh + (size_t)(r0 + 8) * 128 + col) = hi;
                *(uint32_t*)(outl + (size_t)(r0 + 8) * 128 + col) = lo;
            }
        }
    }
}

// ---------- layer-3 pair GEMM: p = h2@Wl3^T, q = h2@Wr3^T + b (stacked rows 512+) --
__global__ __launch_bounds__(256) void k_gemm3_mma(
    const __nv_bfloat16* __restrict__ ah, const __nv_bfloat16* __restrict__ al,
    const float* __restrict__ bias,
    float* __restrict__ p, float* __restrict__ q)
{
    extern __shared__ __nv_bfloat16 smb[];
    const int t    = threadIdx.x;
    const int lane = t & 31;
    const int w    = t >> 5;
    const int wm   = w & 3;
    const int wn   = w >> 2;      // 0 -> p, 1 -> q
    const int row0 = blockIdx.x * 128;

    float c[2][4][4];
    #pragma unroll
    for (int mt = 0; mt < 2; mt++)
        #pragma unroll
        for (int nt = 0; nt < 4; nt++)
            #pragma unroll
            for (int i = 0; i < 4; i++) c[mt][nt][i] = 0.f;

    #pragma unroll 1
    for (int ck = 0; ck < 2; ck++) {
        const int kc = ck * 64;
        load_A_plane(smb, ah, al, row0, kc, t);
        load_W_plane(smb, 512, kc, t);
        __syncthreads();
        mma_chunk(smb, wm, wn, lane, c);
        __syncthreads();
    }

    float* dstm = (wn == 0) ? p : q;
    #pragma unroll
    for (int mt = 0; mt < 2; mt++) {
        int r0 = row0 + wm * 32 + mt * 16 + (lane >> 2);
        #pragma unroll
        for (int nt = 0; nt < 4; nt++) {
            int col = nt * 8 + (lane & 3) * 2;
            float b0 = (wn == 1) ? bias[col]     : 0.f;
            float b1 = (wn == 1) ? bias[col + 1] : 0.f;
            if (r0 < N_NODES)
                *(float2*)(dstm + (size_t)r0 * 32 + col) =
                    make_float2(c[mt][nt][0] + b0, c[mt][nt][1] + b1);
            if (r0 + 8 < N_NODES)
                *(float2*)(dstm + (size_t)(r0 + 8) * 32 + col) =
                    make_float2(c[mt][nt][2] + b0, c[mt][nt][3] + b1);
        }
    }
}

// ---------------- layer-3 aggregation in 32-d + final relu ----------------
__global__ void k_agg3(const float* __restrict__ p, const float* __restrict__ q,
                       float* __restrict__ out) {
    int w    = (blockIdx.x * blockDim.x + threadIdx.x) >> 5;
    int lane = threadIdx.x & 31;
    if (w >= N_NODES) return;

    int e  = g_off[w];
    int e1 = g_off[w + 1];
    float acc = 0.f;
    for (; e + 3 < e1; e += 4) {
        int s0 = g_srcs[e], s1 = g_srcs[e + 1], s2 = g_srcs[e + 2], s3 = g_srcs[e + 3];
        acc += (p[(size_t)s0 * 32 + lane] + p[(size_t)s1 * 32 + lane])
             + (p[(size_t)s2 * 32 + lane] + p[(size_t)s3 * 32 + lane]);
    }
    for (; e < e1; e++) acc += p[(size_t)g_srcs[e] * 32 + lane];

    out[(size_t)w * 32 + lane] = fmaxf(acc * g_inv[w] + q[(size_t)w * 32 + lane], 0.f);
}

// ---------------- launch ----------------
extern "C" void kernel_launch(void* const* d_in, const int* in_sizes, int n_in,
                              void* d_out, int out_size) {
    const float* x   = (const float*)d_in[0];
    const int*   ei  = (const int*)d_in[1];
    const float* Wl1 = (const float*)d_in[2];
    const float* bl1 = (const float*)d_in[3];
    const float* Wr1 = (const float*)d_in[4];
    const float* Wl2 = (const float*)d_in[5];
    const float* bl2 = (const float*)d_in[6];
    const float* Wr2 = (const float*)d_in[7];
    const float* Wl3 = (const float*)d_in[8];
    const float* bl3 = (const float*)d_in[9];
    const float* Wr3 = (const float*)d_in[10];
    float* out = (float*)d_out;

    const int* src = ei;
    const int* dst = ei + N_EDGES;

    cudaFuncSetAttribute(k_gemmJ_mma<true>,  cudaFuncAttributeMaxDynamicSharedMemorySize, SMEM_MMA);
    cudaFuncSetAttribute(k_gemmJ_mma<false>, cudaFuncAttributeMaxDynamicSharedMemorySize, SMEM_MMA);
    cudaFuncSetAttribute(k_gemm3_mma,        cudaFuncAttributeMaxDynamicSharedMemorySize, SMEM_MMA);

    int* deg_p;
    float *h1_p, *p_p, *q_p;
    __nv_bfloat16 *xh_p, *xl_p, *mh_p, *ml_p, *h1h_p, *h1l_p, *h2h_p, *h2l_p;
    cudaGetSymbolAddress((void**)&deg_p, g_deg);
    cudaGetSymbolAddress((void**)&h1_p,  g_h1);
    cudaGetSymbolAddress((void**)&p_p,   g_p);
    cudaGetSymbolAddress((void**)&q_p,   g_q);
    cudaGetSymbolAddress((void**)&xh_p,  g_xh);
    cudaGetSymbolAddress((void**)&xl_p,  g_xl);
    cudaGetSymbolAddress((void**)&mh_p,  g_mh);
    cudaGetSymbolAddress((void**)&ml_p,  g_ml);
    cudaGetSymbolAddress((void**)&h1h_p, g_h1h);
    cudaGetSymbolAddress((void**)&h1l_p, g_h1l);
    cudaGetSymbolAddress((void**)&h2h_p, g_h2h);
    cudaGetSymbolAddress((void**)&h2l_p, g_h2l);

    const int EB = (N_EDGES + 255) / 256;
    const int AB = (N_NODES * 32 + 255) / 256;
    const int SB = (X4 + W4 + 255) / 256;
    dim3 GJ((N_NODES + 127) / 128, 2);
    const int G3 = (N_NODES + 127) / 128;

    // pre-split x + all W into bf16 hi/lo planes
    k_split<<<SB, 256>>>(x, Wl1, Wr1, Wl2, Wr2, Wl3, Wr3);

    // CSR build
    cudaMemsetAsync(deg_p, 0, N_NODES * sizeof(int));
    k_count<<<EB, 256>>>(dst);
    k_scan1<<<SCAN_B, 1024>>>();
    k_scan2<<<1, 64>>>();
    k_scan3<<<(N_NODES + 255) / 256, 256>>>();
    k_scatter<<<EB, 256>>>(src, dst);

    // layer 1
    k_agg<<<AB, 256>>>(x);
    k_gemmJ_mma<true><<<GJ, 256, SMEM_MMA>>>(mh_p, ml_p, xh_p, xl_p, 0, 128, bl1,
                                             h1_p, h1h_p, h1l_p);
    // layer 2
    k_agg<<<AB, 256>>>(h1_p);
    k_gemmJ_mma<false><<<GJ, 256, SMEM_MMA>>>(mh_p, ml_p, h1h_p, h1l_p, 256, 384, bl2,
                                              nullptr, h2h_p, h2l_p);
    // layer 3: project to 32-d (p,q), then aggregate in 32-d
    k_gemm3_mma<<<G3, 256, SMEM_MMA>>>(h2h_p, h2l_p, bl3, p_p, q_p);
    k_agg3<<<AB, 256>>>(p_p, q_p, out);
}